// round 2
// baseline (speedup 1.0000x reference)
#include <cuda_runtime.h>

#define PP 32
#define SS 4
#define HH 256
#define WW 256
#define HW (HH*WW)          // 65536
#define NPIX (SS*HW)        // 262144
#define NOUT (PP*SS*HW)     // 8388608

// Scratch per (p,s,pixel): {acc.rgb = over[max(p-2,0)], T[p]}
__device__ float4 g_data[PP * SS * HW];   // 134 MB
// over[P-1] per (s,pixel)  (bro channels) — 4 MB, L2-resident in pass2
__device__ float4 g_bro[SS * HW];

// ---------------------------------------------------------------------------
// Pass 1: 32-plane alpha-compositing scan per (s,pixel).
// ---------------------------------------------------------------------------
__global__ void __launch_bounds__(256)
pass1_kernel(const float* __restrict__ colors,
             const float* __restrict__ alphas)
{
    int idx = blockIdx.x * blockDim.x + threadIdx.x;   // s*HW + pix
    if (idx >= NPIX) return;

    float a[PP];
    #pragma unroll
    for (int p = 0; p < PP; p++)
        a[p] = __ldcs(alphas + (size_t)p * NPIX + idx);

    // suffix transmittance: T[p] = prod_{j>p} (1 - a[j])
    float T[PP];
    {
        float t = 1.0f;
        #pragma unroll
        for (int p = PP - 1; p >= 0; p--) { T[p] = t; t *= (1.0f - a[p]); }
    }

    float ax = 0.f, ay = 0.f, az = 0.f;          // over after plane p
    float p1x = 0.f, p1y = 0.f, p1z = 0.f;       // over[p-1]
    float p2x = 0.f, p2y = 0.f, p2z = 0.f;       // over[p-2]

    #pragma unroll
    for (int p = 0; p < PP; p++) {
        p2x = p1x; p2y = p1y; p2z = p1z;
        p1x = ax;  p1y = ay;  p1z = az;

        const float* c = colors + ((size_t)p * NPIX + idx) * 3;
        float ap  = a[p];
        float cap = 1.0f - ap;
        ax = fmaf(ax, cap, __ldcs(c + 0) * ap);
        ay = fmaf(ay, cap, __ldcs(c + 1) * ap);
        az = fmaf(az, cap, __ldcs(c + 2) * ap);

        // acc[p] = over[max(p-2,0)]
        float sx, sy, sz;
        if (p == 0)      { sx = ax;  sy = ay;  sz = az;  }
        else if (p == 1) { sx = p1x; sy = p1y; sz = p1z; }
        else             { sx = p2x; sy = p2y; sz = p2z; }

        __stcs(&g_data[(size_t)p * NPIX + idx], make_float4(sx, sy, sz, T[p]));
    }
    // bro = over[P-1]
    g_bro[idx] = make_float4(ax, ay, az, 0.f);
}

// ---------------------------------------------------------------------------
// Pass 2: per-(p,s) affine warp + bilinear gather + write (P,S,10,H,W).
// One block = 256 consecutive pixels of one (p,s). Thread 0 computes the
// 12 warp coefficients (K_src @ R @ K_tgt^-1 * d  |  K_src @ t).
// ---------------------------------------------------------------------------
__global__ void __launch_bounds__(256)
pass2_kernel(const float* __restrict__ imgs_src,
             const float* __restrict__ mpi_planes,
             const float* __restrict__ pose_tgt,
             const float* __restrict__ intrins_src,
             const float* __restrict__ intrins_tgt,
             float* __restrict__ out)
{
    __shared__ float w[12];

    int b   = blockIdx.x;
    int ps  = b >> 8;                         // 256 blocks per (p,s)
    int pix = ((b & 255) << 8) + threadIdx.x;
    int s   = ps & (SS - 1);
    int p   = ps >> 2;

    if (threadIdx.x == 0) {
        float Kt[9];
        #pragma unroll
        for (int i = 0; i < 9; i++) Kt[i] = intrins_tgt[i];
        float det = Kt[0]*(Kt[4]*Kt[8]-Kt[5]*Kt[7])
                  - Kt[1]*(Kt[3]*Kt[8]-Kt[5]*Kt[6])
                  + Kt[2]*(Kt[3]*Kt[7]-Kt[4]*Kt[6]);
        float id = 1.0f / det;
        float inv[9];
        inv[0]=(Kt[4]*Kt[8]-Kt[5]*Kt[7])*id;
        inv[1]=(Kt[2]*Kt[7]-Kt[1]*Kt[8])*id;
        inv[2]=(Kt[1]*Kt[5]-Kt[2]*Kt[4])*id;
        inv[3]=(Kt[5]*Kt[6]-Kt[3]*Kt[8])*id;
        inv[4]=(Kt[0]*Kt[8]-Kt[2]*Kt[6])*id;
        inv[5]=(Kt[2]*Kt[3]-Kt[0]*Kt[5])*id;
        inv[6]=(Kt[3]*Kt[7]-Kt[4]*Kt[6])*id;
        inv[7]=(Kt[1]*Kt[6]-Kt[0]*Kt[7])*id;
        inv[8]=(Kt[0]*Kt[4]-Kt[1]*Kt[3])*id;

        const float* Ks   = intrins_src + s * 9;
        const float* pose = pose_tgt   + s * 16;

        float A[9], bb[3];
        #pragma unroll
        for (int i = 0; i < 3; i++) {
            #pragma unroll
            for (int j = 0; j < 3; j++) {
                float acc = 0.f;
                #pragma unroll
                for (int k = 0; k < 3; k++) acc += Ks[i*3+k] * pose[k*4+j];
                A[i*3+j] = acc;
            }
            float accb = 0.f;
            #pragma unroll
            for (int k = 0; k < 3; k++) accb += Ks[i*3+k] * pose[k*4+3];
            bb[i] = accb;
        }
        float d = mpi_planes[p];
        #pragma unroll
        for (int i = 0; i < 3; i++)
            #pragma unroll
            for (int j = 0; j < 3; j++) {
                float acc = 0.f;
                #pragma unroll
                for (int k = 0; k < 3; k++) acc += A[i*3+k] * inv[k*3+j];
                w[i*3+j] = acc * d;
            }
        w[9] = bb[0]; w[10] = bb[1]; w[11] = bb[2];
    }
    __syncthreads();

    float fx = (float)(pix & (WW - 1));
    float fy = (float)(pix >> 8);

    float u0 = fmaf(w[0], fx, fmaf(w[1], fy, w[2])) + w[9];
    float u1 = fmaf(w[3], fx, fmaf(w[4], fy, w[5])) + w[10];
    float u2 = fmaf(w[6], fx, fmaf(w[7], fy, w[8])) + w[11];
    float z  = u2 + 1e-10f;
    float ix = u0 / z;
    float iy = u1 / z;

    float x0f = floorf(ix), y0f = floorf(iy);
    float wx1 = ix - x0f, wy1 = iy - y0f;
    float wx0 = 1.0f - wx1, wy0 = 1.0f - wy1;

    const size_t basep = (size_t)ps * HW;   // this (p,s) plane in g_data
    const int    bases = s * HW;            // src / bro slice

    float o[10];
    #pragma unroll
    for (int c = 0; c < 10; c++) o[c] = 0.f;

    #pragma unroll
    for (int cy = 0; cy < 2; cy++) {
        float yyf = y0f + (float)cy;
        float wy  = cy ? wy1 : wy0;
        #pragma unroll
        for (int cx = 0; cx < 2; cx++) {
            float xxf = x0f + (float)cx;
            bool valid = (xxf >= 0.f) & (xxf <= (float)(WW - 1)) &
                         (yyf >= 0.f) & (yyf <= (float)(HH - 1));
            if (!valid) continue;
            float wgt = (cx ? wx1 : wx0) * wy;
            int off = (int)yyf * WW + (int)xxf;

            float4 fD = __ldg(&g_data[basep + off]);   // acc.rgb, T
            float4 fB = __ldg(&g_bro[bases + off]);    // bro.rgb (L2-resident)
            const float* sp = imgs_src + (size_t)(bases + off) * 3;

            o[0] = fmaf(wgt, fD.w, o[0]);
            o[1] = fmaf(wgt, fD.x, o[1]);
            o[2] = fmaf(wgt, fD.y, o[2]);
            o[3] = fmaf(wgt, fD.z, o[3]);
            o[4] = fmaf(wgt, fB.x, o[4]);
            o[5] = fmaf(wgt, fB.y, o[5]);
            o[6] = fmaf(wgt, fB.z, o[6]);
            o[7] = fmaf(wgt, __ldg(sp + 0), o[7]);
            o[8] = fmaf(wgt, __ldg(sp + 1), o[8]);
            o[9] = fmaf(wgt, __ldg(sp + 2), o[9]);
        }
    }

    #pragma unroll
    for (int c = 0; c < 10; c++)
        __stcs(&out[((size_t)ps * 10 + c) * HW + pix], o[c]);
}

// ---------------------------------------------------------------------------
extern "C" void kernel_launch(void* const* d_in, const int* in_sizes, int n_in,
                              void* d_out, int out_size)
{
    const float* colors      = (const float*)d_in[0];  // (P,S,H,W,3)
    const float* alphas      = (const float*)d_in[1];  // (P,S,H,W)
    const float* imgs_src    = (const float*)d_in[2];  // (S,H,W,3)
    const float* mpi_planes  = (const float*)d_in[3];  // (P,)
    const float* pose_tgt    = (const float*)d_in[4];  // (S,4,4)
    const float* intrins_src = (const float*)d_in[5];  // (S,3,3)
    const float* intrins_tgt = (const float*)d_in[6];  // (3,3)
    float* out = (float*)d_out;                        // (P,S,10,H,W)

    pass1_kernel<<<NPIX / 256, 256>>>(colors, alphas);
    pass2_kernel<<<NOUT / 256, 256>>>(imgs_src, mpi_planes, pose_tgt,
                                      intrins_src, intrins_tgt, out);
}

// round 3
// speedup vs baseline: 1.1459x; 1.1459x over previous
#include <cuda_runtime.h>
#include <cuda_fp16.h>

#define PP 32
#define SS 4
#define HH 256
#define WW 256
#define HW (HH*WW)          // 65536
#define NPIX (SS*HW)        // 262144
#define NOUT (PP*SS*HW)     // 8388608

// Scratch per (p,s,pixel): two half2 = {acc.r,acc.g | acc.b,T}  (8 B)
__device__ uint2 g_data[(size_t)PP * SS * HW];   // 67 MB
// Per (s,pixel): {bro.r,bro.g | bro.b,src.r | src.g,src.b | pad} (16 B, L2-resident)
__device__ uint4 g_bs[SS * HW];                  // 4 MB

static __device__ __forceinline__ unsigned pack2(float a, float b) {
    __half2 h = __floats2half2_rn(a, b);
    return *reinterpret_cast<unsigned*>(&h);
}
static __device__ __forceinline__ float2 unpack2(unsigned u) {
    __half2 h = *reinterpret_cast<__half2*>(&u);
    return __half22float2(h);
}

// ---------------------------------------------------------------------------
// Pass 1: 32-plane alpha-compositing scan per (s,pixel); emits fp16 records.
// ---------------------------------------------------------------------------
__global__ void __launch_bounds__(256)
pass1_kernel(const float* __restrict__ colors,
             const float* __restrict__ alphas,
             const float* __restrict__ imgs_src)
{
    int idx = blockIdx.x * blockDim.x + threadIdx.x;   // s*HW + pix
    if (idx >= NPIX) return;

    float a[PP];
    #pragma unroll
    for (int p = 0; p < PP; p++)
        a[p] = __ldcs(alphas + (size_t)p * NPIX + idx);

    // suffix transmittance: T[p] = prod_{j>p} (1 - a[j])
    float T[PP];
    {
        float t = 1.0f;
        #pragma unroll
        for (int p = PP - 1; p >= 0; p--) { T[p] = t; t *= (1.0f - a[p]); }
    }

    float ax = 0.f, ay = 0.f, az = 0.f;          // over after plane p
    float p1x = 0.f, p1y = 0.f, p1z = 0.f;       // over[p-1]
    float p2x = 0.f, p2y = 0.f, p2z = 0.f;       // over[p-2]

    #pragma unroll
    for (int p = 0; p < PP; p++) {
        p2x = p1x; p2y = p1y; p2z = p1z;
        p1x = ax;  p1y = ay;  p1z = az;

        const float* c = colors + ((size_t)p * NPIX + idx) * 3;
        float ap  = a[p];
        float cap = 1.0f - ap;
        ax = fmaf(ax, cap, __ldcs(c + 0) * ap);
        ay = fmaf(ay, cap, __ldcs(c + 1) * ap);
        az = fmaf(az, cap, __ldcs(c + 2) * ap);

        // acc[p] = over[max(p-2,0)]
        float sx, sy, sz;
        if (p == 0)      { sx = ax;  sy = ay;  sz = az;  }
        else if (p == 1) { sx = p1x; sy = p1y; sz = p1z; }
        else             { sx = p2x; sy = p2y; sz = p2z; }

        __stcs(&g_data[(size_t)p * NPIX + idx],
               make_uint2(pack2(sx, sy), pack2(sz, T[p])));
    }

    // bro = over[P-1]; pack with src image
    const float* sp = imgs_src + (size_t)idx * 3;
    float s0 = __ldg(sp + 0), s1 = __ldg(sp + 1), s2 = __ldg(sp + 2);
    g_bs[idx] = make_uint4(pack2(ax, ay), pack2(az, s0), pack2(s1, s2), 0u);
}

// ---------------------------------------------------------------------------
// Pass 2: per-(p,s) warp + bilinear gather + write (P,S,10,H,W).
// One block = 256 consecutive pixels of one (p,s); thread 0 builds the
// 12 warp coefficients (K_src @ R @ K_tgt^-1 * d  |  K_src @ t).
// ---------------------------------------------------------------------------
__global__ void __launch_bounds__(256)
pass2_kernel(const float* __restrict__ mpi_planes,
             const float* __restrict__ pose_tgt,
             const float* __restrict__ intrins_src,
             const float* __restrict__ intrins_tgt,
             float* __restrict__ out)
{
    __shared__ float w[12];

    int b   = blockIdx.x;
    int ps  = b >> 8;                         // 256 blocks per (p,s)
    int pix = ((b & 255) << 8) + threadIdx.x;
    int s   = ps & (SS - 1);
    int p   = ps >> 2;

    if (threadIdx.x == 0) {
        float Kt[9];
        #pragma unroll
        for (int i = 0; i < 9; i++) Kt[i] = intrins_tgt[i];
        float det = Kt[0]*(Kt[4]*Kt[8]-Kt[5]*Kt[7])
                  - Kt[1]*(Kt[3]*Kt[8]-Kt[5]*Kt[6])
                  + Kt[2]*(Kt[3]*Kt[7]-Kt[4]*Kt[6]);
        float id = 1.0f / det;
        float inv[9];
        inv[0]=(Kt[4]*Kt[8]-Kt[5]*Kt[7])*id;
        inv[1]=(Kt[2]*Kt[7]-Kt[1]*Kt[8])*id;
        inv[2]=(Kt[1]*Kt[5]-Kt[2]*Kt[4])*id;
        inv[3]=(Kt[5]*Kt[6]-Kt[3]*Kt[8])*id;
        inv[4]=(Kt[0]*Kt[8]-Kt[2]*Kt[6])*id;
        inv[5]=(Kt[2]*Kt[3]-Kt[0]*Kt[5])*id;
        inv[6]=(Kt[3]*Kt[7]-Kt[4]*Kt[6])*id;
        inv[7]=(Kt[1]*Kt[6]-Kt[0]*Kt[7])*id;
        inv[8]=(Kt[0]*Kt[4]-Kt[1]*Kt[3])*id;

        const float* Ks   = intrins_src + s * 9;
        const float* pose = pose_tgt   + s * 16;

        float A[9], bb[3];
        #pragma unroll
        for (int i = 0; i < 3; i++) {
            #pragma unroll
            for (int j = 0; j < 3; j++) {
                float acc = 0.f;
                #pragma unroll
                for (int k = 0; k < 3; k++) acc += Ks[i*3+k] * pose[k*4+j];
                A[i*3+j] = acc;
            }
            float accb = 0.f;
            #pragma unroll
            for (int k = 0; k < 3; k++) accb += Ks[i*3+k] * pose[k*4+3];
            bb[i] = accb;
        }
        float d = mpi_planes[p];
        #pragma unroll
        for (int i = 0; i < 3; i++)
            #pragma unroll
            for (int j = 0; j < 3; j++) {
                float acc = 0.f;
                #pragma unroll
                for (int k = 0; k < 3; k++) acc += A[i*3+k] * inv[k*3+j];
                w[i*3+j] = acc * d;
            }
        w[9] = bb[0]; w[10] = bb[1]; w[11] = bb[2];
    }
    __syncthreads();

    float fx = (float)(pix & (WW - 1));
    float fy = (float)(pix >> 8);

    float u0 = fmaf(w[0], fx, fmaf(w[1], fy, w[2])) + w[9];
    float u1 = fmaf(w[3], fx, fmaf(w[4], fy, w[5])) + w[10];
    float u2 = fmaf(w[6], fx, fmaf(w[7], fy, w[8])) + w[11];
    float z  = u2 + 1e-10f;
    float ix = u0 / z;
    float iy = u1 / z;

    float x0f = floorf(ix), y0f = floorf(iy);
    float wx1 = ix - x0f, wy1 = iy - y0f;
    float wx0 = 1.0f - wx1, wy0 = 1.0f - wy1;

    const size_t basep = (size_t)ps * HW;   // this (p,s) plane in g_data
    const int    bases = s * HW;            // bro/src slice

    float o[10];
    #pragma unroll
    for (int c = 0; c < 10; c++) o[c] = 0.f;

    #pragma unroll
    for (int cy = 0; cy < 2; cy++) {
        float yyf = y0f + (float)cy;
        float wy  = cy ? wy1 : wy0;
        #pragma unroll
        for (int cx = 0; cx < 2; cx++) {
            float xxf = x0f + (float)cx;
            bool valid = (xxf >= 0.f) & (xxf <= (float)(WW - 1)) &
                         (yyf >= 0.f) & (yyf <= (float)(HH - 1));
            if (!valid) continue;
            float wgt = (cx ? wx1 : wx0) * wy;
            int off = (int)yyf * WW + (int)xxf;

            uint2 dU = __ldg(&g_data[basep + off]);
            uint4 bU = __ldg(&g_bs[bases + off]);

            float2 d0 = unpack2(dU.x);      // acc.r, acc.g
            float2 d1 = unpack2(dU.y);      // acc.b, T
            float2 b0 = unpack2(bU.x);      // bro.r, bro.g
            float2 b1 = unpack2(bU.y);      // bro.b, src.r
            float2 b2 = unpack2(bU.z);      // src.g, src.b

            o[0] = fmaf(wgt, d1.y, o[0]);
            o[1] = fmaf(wgt, d0.x, o[1]);
            o[2] = fmaf(wgt, d0.y, o[2]);
            o[3] = fmaf(wgt, d1.x, o[3]);
            o[4] = fmaf(wgt, b0.x, o[4]);
            o[5] = fmaf(wgt, b0.y, o[5]);
            o[6] = fmaf(wgt, b1.x, o[6]);
            o[7] = fmaf(wgt, b1.y, o[7]);
            o[8] = fmaf(wgt, b2.x, o[8]);
            o[9] = fmaf(wgt, b2.y, o[9]);
        }
    }

    #pragma unroll
    for (int c = 0; c < 10; c++)
        __stcs(&out[((size_t)ps * 10 + c) * HW + pix], o[c]);
}

// ---------------------------------------------------------------------------
extern "C" void kernel_launch(void* const* d_in, const int* in_sizes, int n_in,
                              void* d_out, int out_size)
{
    const float* colors      = (const float*)d_in[0];  // (P,S,H,W,3)
    const float* alphas      = (const float*)d_in[1];  // (P,S,H,W)
    const float* imgs_src    = (const float*)d_in[2];  // (S,H,W,3)
    const float* mpi_planes  = (const float*)d_in[3];  // (P,)
    const float* pose_tgt    = (const float*)d_in[4];  // (S,4,4)
    const float* intrins_src = (const float*)d_in[5];  // (S,3,3)
    const float* intrins_tgt = (const float*)d_in[6];  // (3,3)
    float* out = (float*)d_out;                        // (P,S,10,H,W)

    pass1_kernel<<<NPIX / 256, 256>>>(colors, alphas, imgs_src);
    pass2_kernel<<<NOUT / 256, 256>>>(mpi_planes, pose_tgt,
                                      intrins_src, intrins_tgt, out);
}